// round 11
// baseline (speedup 1.0000x reference)
#include <cuda_runtime.h>
#include <cuda_fp16.h>
#include <cstdint>

// ============================================================================
// Problem constants
// ============================================================================
#define B_TOTAL   16384
#define NSTATES   4096
#define N_ACT     4
#define NKEYS     (NSTATES*N_ACT)     // 16384 (action*4096 + state)
#define GTOT      768
#define TILE_M    128
#define MAX_TILES 132                 // worst case: all pairs unique + per-action pad
#define P_MAX     (MAX_TILES*TILE_M)  // 16896
#define NW        (NSTATES*GTOT)      // 3145728
#define ND        655360              // 4*(256^2+256^2+128^2+128^2)

// smem tile: 128 rows x 64 halves, padded row stride 72 halves (144B).
// 144 mod 128 = 16 -> 8 consecutive rows land on 8 distinct 16B banks: conflict-free ldmatrix.
#define SROW      72
#define STAGE_H   (128*SROW)          // halves per operand tile (9216)
#define STAGE_B   (STAGE_H*2)         // bytes per operand tile (18432)
#define SMEM_TOT  (4*STAGE_B)         // A0 A1 B0 B1 = 73728 B (dynamic, opt-in)

#define SCAN_BLKS 16                  // 1024 keys per block; 4 blocks per action

// ============================================================================
// PTX helpers (baseline sm_80+ features only — target is compute_103 non-'a')
// ============================================================================
__device__ __forceinline__ uint32_t smem_to_u32(const void* smem_ptr) {
    uint32_t addr;
    asm("{ .reg .u64 tmp; cvta.to.shared.u64 tmp, %1; cvt.u32.u64 %0, tmp; }"
        : "=r"(addr) : "l"(smem_ptr));
    return addr;
}
__device__ __forceinline__ void cp_async16(uint32_t s, const void* g) {
    asm volatile("cp.async.cg.shared.global [%0], [%1], 16;" :: "r"(s), "l"(g));
}
#define CP_COMMIT() asm volatile("cp.async.commit_group;" ::: "memory")
#define CP_WAIT(n)  asm volatile("cp.async.wait_group %0;" :: "n"(n) : "memory")

__device__ __forceinline__ void ldsm_x4(uint32_t* r, uint32_t addr) {
    asm volatile("ldmatrix.sync.aligned.m8n8.x4.shared.b16 {%0,%1,%2,%3}, [%4];"
        : "=r"(r[0]), "=r"(r[1]), "=r"(r[2]), "=r"(r[3]) : "r"(addr));
}
__device__ __forceinline__ void mma16816(float* c, const uint32_t* a,
                                         uint32_t b0, uint32_t b1) {
    asm volatile(
        "mma.sync.aligned.m16n8k16.row.col.f32.f16.f16.f32 "
        "{%0,%1,%2,%3}, {%4,%5,%6,%7}, {%8,%9}, {%0,%1,%2,%3};"
        : "+f"(c[0]), "+f"(c[1]), "+f"(c[2]), "+f"(c[3])
        : "r"(a[0]), "r"(a[1]), "r"(a[2]), "r"(a[3]), "r"(b0), "r"(b1));
}
__device__ __forceinline__ uint32_t pack_h2(float a, float b) {
    __half2 h = __floats2half2_rn(a, b);
    return *reinterpret_cast<uint32_t*>(&h);
}

// ============================================================================
// Device scratch (static globals — no runtime allocation)
// ============================================================================
__device__ __align__(128) __half d_Wh[NW];                       // W_cls fp16
__device__ __align__(128) __half d_Dh[ND];                       // D banks fp16
__device__ __align__(128) __half d_Ge[(size_t)P_MAX * GTOT];     // gathered emb (unique) fp16
__device__ __align__(128) __half d_Gh[(size_t)P_MAX * GTOT];     // g_next (unique) fp16

__device__ __align__(16) int d_hist[NKEYS];  // key -> multiplicity
__device__ int d_cur[NKEYS];        // scatter cursor per key
__device__ int d_roff[NKEYS];       // key -> offset into d_rows
__device__ int d_rows[B_TOTAL];     // original row ids, grouped by key
__device__ int d_srow[P_MAX];       // unique slot -> state (-1 pad)
__device__ int d_uroff[P_MAX];      // unique slot -> offset into d_rows
__device__ int d_ucnt[P_MAX];       // unique slot -> multiplicity (0 pad)
__device__ int d_pstart[5];         // 128-aligned padded per-action starts, [4]=total
__device__ int d_bU[SCAN_BLKS];     // per-scan-block unique count
__device__ int d_bT[SCAN_BLKS];     // per-scan-block total count

// ============================================================================
// Pre-pass: convert fp32->fp16; zero/init; key histogram; scan; scatter; gather
// ============================================================================
__global__ void k_conv(const float* __restrict__ W,
                       const float* __restrict__ D0, const float* __restrict__ D1,
                       const float* __restrict__ D2, const float* __restrict__ D3) {
    int i = blockIdx.x * blockDim.x + threadIdx.x;
    const int total = NW + ND;
    for (; i < total; i += gridDim.x * blockDim.x) {
        if (i < NW) {
            d_Wh[i] = __float2half_rn(W[i]);
        } else {
            int j = i - NW;
            const float* src; int o;
            if      (j < 262144) { src = D0; o = j; }
            else if (j < 524288) { src = D1; o = j - 262144; }
            else if (j < 589824) { src = D2; o = j - 524288; }
            else                 { src = D3; o = j - 589824; }
            d_Dh[j] = __float2half_rn(src[o]);
        }
    }
}

__global__ void k_zero() {
    int i = blockIdx.x * 256 + threadIdx.x;
    if (i < NKEYS) { d_hist[i] = 0; d_cur[i] = 0; }
    if (i < P_MAX) { d_srow[i] = -1; d_ucnt[i] = 0; d_uroff[i] = 0; }
}

__global__ void k_hist(const int* __restrict__ act, const int* __restrict__ state) {
    int i = blockIdx.x * 256 + threadIdx.x;
    int key = act[i] * NSTATES + state[i];
    atomicAdd(&d_hist[key], 1);
}

// Phase A: 16 blocks x 256 threads, 4 keys/thread -> per-block {unique, total} sums
__global__ void k_scanA() {
    __shared__ int sU[8], sT[8];
    const int t = threadIdx.x, lane = t & 31, warp = t >> 5;
    const int k0 = (blockIdx.x * 256 + t) * 4;
    int4 x = *(const int4*)(d_hist + k0);
    int nu = (x.x != 0) + (x.y != 0) + (x.z != 0) + (x.w != 0);
    int nt = x.x + x.y + x.z + x.w;
#pragma unroll
    for (int o = 16; o > 0; o >>= 1) {
        nu += __shfl_down_sync(~0u, nu, o);
        nt += __shfl_down_sync(~0u, nt, o);
    }
    if (lane == 0) { sU[warp] = nu; sT[warp] = nt; }
    __syncthreads();
    if (t == 0) {
        int tu = 0, tt = 0;
#pragma unroll
        for (int w = 0; w < 8; w++) { tu += sU[w]; tt += sT[w]; }
        d_bU[blockIdx.x] = tu;
        d_bT[blockIdx.x] = tt;
    }
}

// Phase B: 16 blocks; each recomputes the 16-entry prefix, scans its 1024 keys, writes.
__global__ void k_scanB() {
    __shared__ int wU[8], wT[8];
    __shared__ int base_u, base_r, pstS[5];
    const int t = threadIdx.x, lane = t & 31, warp = t >> 5;
    const int blk = blockIdx.x;

    if (t == 0) {
        int bU[SCAN_BLKS], bT[SCAN_BLKS];
#pragma unroll
        for (int b = 0; b < SCAN_BLKS; b++) { bU[b] = d_bU[b]; bT[b] = d_bT[b]; }
        // padded per-action bases
        int p = 0;
#pragma unroll
        for (int a = 0; a < N_ACT; a++) {
            pstS[a] = p;
            int ua = bU[a * 4] + bU[a * 4 + 1] + bU[a * 4 + 2] + bU[a * 4 + 3];
            p += ((ua + TILE_M - 1) / TILE_M) * TILE_M;
        }
        pstS[4] = p;
        if (blk == 0) {
#pragma unroll
            for (int a = 0; a <= N_ACT; a++) d_pstart[a] = pstS[a];
        }
        // this block's unique base (within its action) and global rows base
        int a = blk >> 2;
        int u = pstS[a];
        for (int b = a * 4; b < blk; b++) u += bU[b];
        int r = 0;
        for (int b = 0; b < blk; b++) r += bT[b];
        base_u = u; base_r = r;
    }
    __syncthreads();

    const int k0 = (blk * 256 + t) * 4;
    int4 x = *(const int4*)(d_hist + k0);
    int h[4] = { x.x, x.y, x.z, x.w };
    int nu = (h[0] != 0) + (h[1] != 0) + (h[2] != 0) + (h[3] != 0);
    int nt = h[0] + h[1] + h[2] + h[3];
    int su = nu, st = nt;
#pragma unroll
    for (int o = 1; o < 32; o <<= 1) {
        int vu = __shfl_up_sync(~0u, su, o);
        int vt = __shfl_up_sync(~0u, st, o);
        if (lane >= o) { su += vu; st += vt; }
    }
    if (lane == 31) { wU[warp] = su; wT[warp] = st; }
    __syncthreads();
    int wexU = 0, wexT = 0;
    for (int w = 0; w < warp; w++) { wexU += wU[w]; wexT += wT[w]; }
    int u = base_u + wexU + (su - nu);
    int r = base_r + wexT + (st - nt);
#pragma unroll
    for (int i = 0; i < 4; i++) {
        int k = k0 + i;
        if (h[i]) {
            d_roff[k] = r;
            d_srow[u] = k & (NSTATES - 1);
            d_uroff[u] = r; d_ucnt[u] = h[i];
            u++; r += h[i];
        }
    }
}

__global__ void k_scatter(const int* __restrict__ act, const int* __restrict__ state) {
    int i = blockIdx.x * 256 + threadIdx.x;
    int key = act[i] * NSTATES + state[i];
    int pos = atomicAdd(&d_cur[key], 1);
    d_rows[d_roff[key] + pos] = i;
}

// gather emb rows into unique fp16 buffer d_Ge (zeros for pad rows)
__global__ void k_gather(const float* __restrict__ emb) {
    int i = blockIdx.x * 256 + threadIdx.x;     // one uint4 (8 halves) per thread
    int krow = i / (GTOT / 8);
    int cu   = i - krow * (GTOT / 8);
    if (krow >= d_pstart[4]) return;
    int srow = d_srow[krow];
    uint4 h;
    if (srow >= 0) {
        const float4* p = (const float4*)(emb + (size_t)srow * GTOT + cu * 8);
        float4 x0 = p[0], x1 = p[1];
        h.x = pack_h2(x0.x, x0.y); h.y = pack_h2(x0.z, x0.w);
        h.z = pack_h2(x1.x, x1.y); h.w = pack_h2(x1.z, x1.w);
    } else {
        h = make_uint4(0, 0, 0, 0);
    }
    *(uint4*)(d_Ge + (size_t)krow * GTOT + cu * 8) = h;
}

// ============================================================================
// Shared GEMM building blocks (BM=BN=128, BK=64, 256 threads, 8 warps 2Mx4N)
// ============================================================================
__device__ __forceinline__ void load_tile64(uint32_t sDst, const __half* gBase,
                                            int rowStride, int kofs, int tid) {
#pragma unroll
    for (int i = 0; i < 4; i++) {
        int idx = tid + i * 256;            // 0..1023 -> 128 rows x 8 16B chunks
        int row = idx >> 3, cb = idx & 7;
        cp_async16(sDst + (uint32_t)(row * SROW + cb * 8) * 2u,
                   gBase + (size_t)row * rowStride + kofs + cb * 8);
    }
}

__device__ __forceinline__ void gemm_stage64(uint32_t sA, uint32_t sB, int wm, int wn,
                                             int lane, float (*c)[4][4]) {
#pragma unroll
    for (int ks = 0; ks < 4; ks++) {
        uint32_t a[4][4];
#pragma unroll
        for (int mt = 0; mt < 4; mt++) {
            int row = wm * 64 + mt * 16 + (lane & 15);
            int col = ks * 16 + ((lane >> 4) << 3);
            ldsm_x4(a[mt], sA + (uint32_t)(row * SROW + col) * 2u);
        }
#pragma unroll
        for (int g2 = 0; g2 < 2; g2++) {
            uint32_t b[4];
            int nrow = wn * 32 + g2 * 16 + (lane & 7) + ((lane >> 4) & 1) * 8;
            int col  = ks * 16 + ((lane >> 3) & 1) * 8;
            ldsm_x4(b, sB + (uint32_t)(nrow * SROW + col) * 2u);
#pragma unroll
            for (int mt = 0; mt < 4; mt++) {
                mma16816(c[mt][g2 * 2 + 0], a[mt], b[0], b[1]);
                mma16816(c[mt][g2 * 2 + 1], a[mt], b[2], b[3]);
            }
        }
    }
}

// ============================================================================
// Transition kernel: per (128-row unique tile, module-coltile) HMMA GEMM
//   delta[r,j] = sum_i g[r,i] * D[a][j,i];  g_next = clip(g + delta, -1, 1)
// grid.y jobs: 0,1 -> f0 col0/1; 2,3 -> f1 col0/1; 4 -> f2; 5 -> f3
// ============================================================================
__global__ void __launch_bounds__(256, 2) k_trans(float* __restrict__ outg) {
    extern __shared__ __align__(16) __half sm[];
    const int row0 = blockIdx.x * TILE_M;
    if (row0 >= d_pstart[4]) return;
    const int jy = blockIdx.y;
    const int f    = (jy < 2) ? 0 : (jy < 4) ? 1 : (jy == 4) ? 2 : 3;
    const int ct   = (jy == 1 || jy == 3) ? 1 : 0;
    const int n    = (f < 2) ? 256 : 128;
    const int koff = (f == 0) ? 0 : (f == 1) ? 256 : (f == 2) ? 512 : 640;
    const int moff = (f == 0) ? 0 : (f == 1) ? 262144 : (f == 2) ? 524288 : 589824;
    const int col0 = ct * 128;

    int a = 0;
    { int p1 = d_pstart[1], p2 = d_pstart[2], p3 = d_pstart[3];
      if (row0 >= p3) a = 3; else if (row0 >= p2) a = 2; else if (row0 >= p1) a = 1; }

    const int tid = threadIdx.x, lane = tid & 31, wid = tid >> 5;
    const int wm = wid & 1, wn = wid >> 1;
    uint32_t sb = smem_to_u32(sm);
    uint32_t sA[2] = { sb,              sb + STAGE_B };
    uint32_t sB[2] = { sb + 2*STAGE_B,  sb + 3*STAGE_B };

    const __half* Ab = d_Ge + (size_t)row0 * GTOT + koff;
    const __half* Bb = d_Dh + (size_t)moff + (size_t)a * n * n + (size_t)col0 * n;

    float c[4][4][4];
#pragma unroll
    for (int i = 0; i < 4; i++)
#pragma unroll
        for (int j = 0; j < 4; j++)
#pragma unroll
            for (int e = 0; e < 4; e++) c[i][j][e] = 0.0f;

    load_tile64(sA[0], Ab, GTOT, 0, tid);
    load_tile64(sB[0], Bb, n,    0, tid);
    CP_COMMIT();
    const int KT = n >> 6;      // 4 or 2
    for (int kc = 0; kc < KT; kc++) {
        int cur = kc & 1;
        if (kc + 1 < KT) {
            load_tile64(sA[cur ^ 1], Ab, GTOT, (kc + 1) * 64, tid);
            load_tile64(sB[cur ^ 1], Bb, n,    (kc + 1) * 64, tid);
            CP_COMMIT();
            CP_WAIT(1);
        } else {
            CP_WAIT(0);
        }
        __syncthreads();
        gemm_stage64(sA[cur], sB[cur], wm, wn, lane, c);
        __syncthreads();
    }

    // epilogue: gn = clip(g + delta); fp16 to unique buf, fp32 fan-out to dup rows
#pragma unroll
    for (int mt = 0; mt < 4; mt++) {
#pragma unroll
        for (int e2 = 0; e2 < 2; e2++) {
            int krow = row0 + wm * 64 + mt * 16 + (lane >> 2) + e2 * 8;
            int cnt  = d_ucnt[krow];
            int roff = d_uroff[krow];
            int cbase = koff + col0 + wn * 32 + 2 * (lane & 3);
            const __half* gp = d_Ge + (size_t)krow * GTOT + cbase;
            __half*       hp = d_Gh + (size_t)krow * GTOT + cbase;
            float2 vals[4];
#pragma unroll
            for (int ng = 0; ng < 4; ng++) {
                __half2 g2v = *(const __half2*)(gp + ng * 8);
                float vx = __low2float(g2v)  + c[mt][ng][e2 * 2 + 0];
                float vy = __high2float(g2v) + c[mt][ng][e2 * 2 + 1];
                vx = fminf(1.0f, fmaxf(-1.0f, vx));
                vy = fminf(1.0f, fmaxf(-1.0f, vy));
                *(__half2*)(hp + ng * 8) = __floats2half2_rn(vx, vy);
                vals[ng].x = vx; vals[ng].y = vy;
            }
            for (int j = 0; j < cnt; j++) {
                int orow = d_rows[roff + j];
                float* op = outg + (size_t)orow * GTOT + cbase;
#pragma unroll
                for (int ng = 0; ng < 4; ng++)
                    *(float2*)(op + ng * 8) = vals[ng];
            }
        }
    }
}

// ============================================================================
// Classifier kernel: logits = g_next @ W^T + b   (128x128 tiles, K=768, BK=64)
// 256 threads, 2 CTAs/SM (cross-CTA latency hiding at barriers — R9 config)
// ============================================================================
__global__ void __launch_bounds__(256, 2) k_cls(const float* __restrict__ bias,
                                                float* __restrict__ out) {
    extern __shared__ __align__(16) __half sm[];
    const int row0 = blockIdx.x * TILE_M;
    if (row0 >= d_pstart[4]) return;
    const int col0 = blockIdx.y * 128;

    const int tid = threadIdx.x, lane = tid & 31, wid = tid >> 5;
    const int wm = wid & 1, wn = wid >> 1;
    uint32_t sb = smem_to_u32(sm);
    uint32_t sA[2] = { sb,              sb + STAGE_B };
    uint32_t sB[2] = { sb + 2*STAGE_B,  sb + 3*STAGE_B };

    const __half* Ab = d_Gh + (size_t)row0 * GTOT;
    const __half* Bb = d_Wh + (size_t)col0 * GTOT;

    float c[4][4][4];
#pragma unroll
    for (int i = 0; i < 4; i++)
#pragma unroll
        for (int j = 0; j < 4; j++)
#pragma unroll
            for (int e = 0; e < 4; e++) c[i][j][e] = 0.0f;

    load_tile64(sA[0], Ab, GTOT, 0, tid);
    load_tile64(sB[0], Bb, GTOT, 0, tid);
    CP_COMMIT();
    const int KT = GTOT >> 6;   // 12
    for (int kc = 0; kc < KT; kc++) {
        int cur = kc & 1;
        if (kc + 1 < KT) {
            load_tile64(sA[cur ^ 1], Ab, GTOT, (kc + 1) * 64, tid);
            load_tile64(sB[cur ^ 1], Bb, GTOT, (kc + 1) * 64, tid);
            CP_COMMIT();
            CP_WAIT(1);
        } else {
            CP_WAIT(0);
        }
        __syncthreads();
        gemm_stage64(sA[cur], sB[cur], wm, wn, lane, c);
        __syncthreads();
    }

    // epilogue: add bias, fan logits out to all duplicate original rows
#pragma unroll
    for (int mt = 0; mt < 4; mt++) {
#pragma unroll
        for (int e2 = 0; e2 < 2; e2++) {
            int krow = row0 + wm * 64 + mt * 16 + (lane >> 2) + e2 * 8;
            int cnt  = d_ucnt[krow];
            if (cnt == 0) continue;
            int roff = d_uroff[krow];
            int cbase = col0 + wn * 32 + 2 * (lane & 3);
            float2 vals[4];
#pragma unroll
            for (int ng = 0; ng < 4; ng++) {
                float2 bv = *(const float2*)(bias + cbase + ng * 8);
                vals[ng].x = c[mt][ng][e2 * 2 + 0] + bv.x;
                vals[ng].y = c[mt][ng][e2 * 2 + 1] + bv.y;
            }
            for (int j = 0; j < cnt; j++) {
                int orow = d_rows[roff + j];
                float* op = out + (size_t)orow * NSTATES + cbase;
#pragma unroll
                for (int ng = 0; ng < 4; ng++)
                    *(float2*)(op + ng * 8) = vals[ng];
            }
        }
    }
}

// ============================================================================
// Host launch (graph-capturable: kernel launches only)
// ============================================================================
extern "C" void kernel_launch(void* const* d_in, const int* in_sizes, int n_in,
                              void* d_out, int out_size) {
    // Identify inputs by element count (unambiguous for this problem):
    //   16384 (x2): current_state_index, action_index   (metadata order: state first)
    //   3145728 (x2): emb, W_cls      4096: b_cls
    //   262144 (x2): D0, D1           65536 (x2): D2, D3
    const int *state = nullptr, *act = nullptr;
    const float *emb = nullptr, *W = nullptr, *bias = nullptr;
    const float *D0 = nullptr, *D1 = nullptr, *D2 = nullptr, *D3 = nullptr;
    for (int i = 0; i < n_in; i++) {
        int s = in_sizes[i];
        const void* p = d_in[i];
        if      (s == 16384)   { if (!state) state = (const int*)p; else act = (const int*)p; }
        else if (s == 3145728) { if (!emb)   emb   = (const float*)p; else W = (const float*)p; }
        else if (s == 4096)    { bias = (const float*)p; }
        else if (s == 262144)  { if (!D0) D0 = (const float*)p; else D1 = (const float*)p; }
        else if (s == 65536)   { if (!D2) D2 = (const float*)p; else D3 = (const float*)p; }
    }

    float* out  = (float*)d_out;                       // logits [16384, 4096]
    float* outg = out + (size_t)B_TOTAL * NSTATES;     // g_next [16384, 768]

    cudaFuncSetAttribute(k_trans, cudaFuncAttributeMaxDynamicSharedMemorySize, SMEM_TOT);
    cudaFuncSetAttribute(k_cls,   cudaFuncAttributeMaxDynamicSharedMemorySize, SMEM_TOT);

    k_conv<<<512, 256>>>(W, D0, D1, D2, D3);
    k_zero<<<(P_MAX + 255) / 256, 256>>>();
    k_hist<<<64, 256>>>(act, state);
    k_scanA<<<SCAN_BLKS, 256>>>();
    k_scanB<<<SCAN_BLKS, 256>>>();
    k_scatter<<<64, 256>>>(act, state);
    k_gather<<<P_MAX * (GTOT / 8) / 256, 256>>>(emb);
    k_trans<<<dim3(MAX_TILES, 6), 256, SMEM_TOT>>>(outg);
    k_cls<<<dim3(MAX_TILES, 32), 256, SMEM_TOT>>>(bias, out);
}

// round 12
// speedup vs baseline: 1.5173x; 1.5173x over previous
#include <cuda_runtime.h>
#include <cuda_fp16.h>
#include <cstdint>

// ============================================================================
// Problem constants
// ============================================================================
#define B_TOTAL   16384
#define NSTATES   4096
#define N_ACT     4
#define NKEYS     (NSTATES*N_ACT)     // 16384 (action*4096 + state)
#define GTOT      768
#define TILE_M    128
#define MAX_TILES 132                 // worst case: all pairs unique + per-action pad
#define P_MAX     (MAX_TILES*TILE_M)  // 16896
#define NW        (NSTATES*GTOT)      // 3145728
#define ND        655360              // 4*(256^2+256^2+128^2+128^2)

// smem tile: 128 rows x 64 halves, padded row stride 72 halves (144B).
// 144 mod 128 = 16 -> 8 consecutive rows land on 8 distinct 16B banks: conflict-free ldmatrix.
#define SROW      72
#define STAGE_H   (128*SROW)          // halves per operand tile (9216)
#define STAGE_B   (STAGE_H*2)         // bytes per operand tile (18432)
#define SMEM_P    (6*STAGE_B)         // 3-stage pipeline: A0..A2 B0..B2 = 110592 B

#define SCAN_BLKS 16                  // 1024 keys per block; 4 blocks per action

// ============================================================================
// PTX helpers (baseline sm_80+ features only — target is compute_103 non-'a')
// ============================================================================
__device__ __forceinline__ uint32_t smem_to_u32(const void* smem_ptr) {
    uint32_t addr;
    asm("{ .reg .u64 tmp; cvta.to.shared.u64 tmp, %1; cvt.u32.u64 %0, tmp; }"
        : "=r"(addr) : "l"(smem_ptr));
    return addr;
}
__device__ __forceinline__ void cp_async16(uint32_t s, const void* g) {
    asm volatile("cp.async.cg.shared.global [%0], [%1], 16;" :: "r"(s), "l"(g));
}
#define CP_COMMIT() asm volatile("cp.async.commit_group;" ::: "memory")
#define CP_WAIT(n)  asm volatile("cp.async.wait_group %0;" :: "n"(n) : "memory")

__device__ __forceinline__ void ldsm_x4(uint32_t* r, uint32_t addr) {
    asm volatile("ldmatrix.sync.aligned.m8n8.x4.shared.b16 {%0,%1,%2,%3}, [%4];"
        : "=r"(r[0]), "=r"(r[1]), "=r"(r[2]), "=r"(r[3]) : "r"(addr));
}
__device__ __forceinline__ void mma16816(float* c, const uint32_t* a,
                                         uint32_t b0, uint32_t b1) {
    asm volatile(
        "mma.sync.aligned.m16n8k16.row.col.f32.f16.f16.f32 "
        "{%0,%1,%2,%3}, {%4,%5,%6,%7}, {%8,%9}, {%0,%1,%2,%3};"
        : "+f"(c[0]), "+f"(c[1]), "+f"(c[2]), "+f"(c[3])
        : "r"(a[0]), "r"(a[1]), "r"(a[2]), "r"(a[3]), "r"(b0), "r"(b1));
}
__device__ __forceinline__ uint32_t pack_h2(float a, float b) {
    __half2 h = __floats2half2_rn(a, b);
    return *reinterpret_cast<uint32_t*>(&h);
}

// ============================================================================
// Device scratch (static globals — no runtime allocation)
// ============================================================================
__device__ __align__(128) __half d_Wh[NW];                       // W_cls fp16
__device__ __align__(128) __half d_Dh[ND];                       // D banks fp16
__device__ __align__(128) __half d_Ge[(size_t)P_MAX * GTOT];     // gathered emb (unique) fp16
__device__ __align__(128) __half d_Gh[(size_t)P_MAX * GTOT];     // g_next (unique) fp16

__device__ __align__(16) int d_hist[NKEYS];  // key -> multiplicity
__device__ int d_cur[NKEYS];        // scatter cursor per key
__device__ int d_roff[NKEYS];       // key -> offset into d_rows
__device__ int d_rows[B_TOTAL];     // original row ids, grouped by key
__device__ int d_srow[P_MAX];       // unique slot -> state (-1 pad)
__device__ int d_uroff[P_MAX];      // unique slot -> offset into d_rows
__device__ int d_ucnt[P_MAX];       // unique slot -> multiplicity (0 pad)
__device__ int d_pstart[5];         // 128-aligned padded per-action starts, [4]=total
__device__ int d_bU[SCAN_BLKS];     // per-scan-block unique count
__device__ int d_bT[SCAN_BLKS];     // per-scan-block total count

// ============================================================================
// Pre-pass: convert fp32->fp16; zero/init; key histogram; scan; scatter; gather
// ============================================================================
__global__ void k_conv(const float* __restrict__ W,
                       const float* __restrict__ D0, const float* __restrict__ D1,
                       const float* __restrict__ D2, const float* __restrict__ D3) {
    int i = blockIdx.x * blockDim.x + threadIdx.x;
    const int total = NW + ND;
    for (; i < total; i += gridDim.x * blockDim.x) {
        if (i < NW) {
            d_Wh[i] = __float2half_rn(W[i]);
        } else {
            int j = i - NW;
            const float* src; int o;
            if      (j < 262144) { src = D0; o = j; }
            else if (j < 524288) { src = D1; o = j - 262144; }
            else if (j < 589824) { src = D2; o = j - 524288; }
            else                 { src = D3; o = j - 589824; }
            d_Dh[j] = __float2half_rn(src[o]);
        }
    }
}

__global__ void k_zero() {
    int i = blockIdx.x * 256 + threadIdx.x;
    if (i < NKEYS) { d_hist[i] = 0; d_cur[i] = 0; }
    if (i < P_MAX) { d_srow[i] = -1; d_ucnt[i] = 0; d_uroff[i] = 0; }
}

__global__ void k_hist(const int* __restrict__ act, const int* __restrict__ state) {
    int i = blockIdx.x * 256 + threadIdx.x;
    int key = act[i] * NSTATES + state[i];
    atomicAdd(&d_hist[key], 1);
}

// Phase A: 16 blocks x 256 threads, 4 keys/thread -> per-block {unique, total} sums
__global__ void k_scanA() {
    __shared__ int sU[8], sT[8];
    const int t = threadIdx.x, lane = t & 31, warp = t >> 5;
    const int k0 = (blockIdx.x * 256 + t) * 4;
    int4 x = *(const int4*)(d_hist + k0);
    int nu = (x.x != 0) + (x.y != 0) + (x.z != 0) + (x.w != 0);
    int nt = x.x + x.y + x.z + x.w;
#pragma unroll
    for (int o = 16; o > 0; o >>= 1) {
        nu += __shfl_down_sync(~0u, nu, o);
        nt += __shfl_down_sync(~0u, nt, o);
    }
    if (lane == 0) { sU[warp] = nu; sT[warp] = nt; }
    __syncthreads();
    if (t == 0) {
        int tu = 0, tt = 0;
#pragma unroll
        for (int w = 0; w < 8; w++) { tu += sU[w]; tt += sT[w]; }
        d_bU[blockIdx.x] = tu;
        d_bT[blockIdx.x] = tt;
    }
}

// Phase B: 16 blocks; each recomputes the 16-entry prefix, scans its 1024 keys, writes.
__global__ void k_scanB() {
    __shared__ int wU[8], wT[8];
    __shared__ int base_u, base_r, pstS[5];
    const int t = threadIdx.x, lane = t & 31, warp = t >> 5;
    const int blk = blockIdx.x;

    if (t == 0) {
        int bU[SCAN_BLKS], bT[SCAN_BLKS];
#pragma unroll
        for (int b = 0; b < SCAN_BLKS; b++) { bU[b] = d_bU[b]; bT[b] = d_bT[b]; }
        int p = 0;
#pragma unroll
        for (int a = 0; a < N_ACT; a++) {
            pstS[a] = p;
            int ua = bU[a * 4] + bU[a * 4 + 1] + bU[a * 4 + 2] + bU[a * 4 + 3];
            p += ((ua + TILE_M - 1) / TILE_M) * TILE_M;
        }
        pstS[4] = p;
        if (blk == 0) {
#pragma unroll
            for (int a = 0; a <= N_ACT; a++) d_pstart[a] = pstS[a];
        }
        int a = blk >> 2;
        int u = pstS[a];
        for (int b = a * 4; b < blk; b++) u += bU[b];
        int r = 0;
        for (int b = 0; b < blk; b++) r += bT[b];
        base_u = u; base_r = r;
    }
    __syncthreads();

    const int k0 = (blk * 256 + t) * 4;
    int4 x = *(const int4*)(d_hist + k0);
    int h[4] = { x.x, x.y, x.z, x.w };
    int nu = (h[0] != 0) + (h[1] != 0) + (h[2] != 0) + (h[3] != 0);
    int nt = h[0] + h[1] + h[2] + h[3];
    int su = nu, st = nt;
#pragma unroll
    for (int o = 1; o < 32; o <<= 1) {
        int vu = __shfl_up_sync(~0u, su, o);
        int vt = __shfl_up_sync(~0u, st, o);
        if (lane >= o) { su += vu; st += vt; }
    }
    if (lane == 31) { wU[warp] = su; wT[warp] = st; }
    __syncthreads();
    int wexU = 0, wexT = 0;
    for (int w = 0; w < warp; w++) { wexU += wU[w]; wexT += wT[w]; }
    int u = base_u + wexU + (su - nu);
    int r = base_r + wexT + (st - nt);
#pragma unroll
    for (int i = 0; i < 4; i++) {
        int k = k0 + i;
        if (h[i]) {
            d_roff[k] = r;
            d_srow[u] = k & (NSTATES - 1);
            d_uroff[u] = r; d_ucnt[u] = h[i];
            u++; r += h[i];
        }
    }
}

__global__ void k_scatter(const int* __restrict__ act, const int* __restrict__ state) {
    int i = blockIdx.x * 256 + threadIdx.x;
    int key = act[i] * NSTATES + state[i];
    int pos = atomicAdd(&d_cur[key], 1);
    d_rows[d_roff[key] + pos] = i;
}

// gather emb rows into unique fp16 buffer d_Ge (zeros for pad rows)
__global__ void k_gather(const float* __restrict__ emb) {
    int i = blockIdx.x * 256 + threadIdx.x;     // one uint4 (8 halves) per thread
    int krow = i / (GTOT / 8);
    int cu   = i - krow * (GTOT / 8);
    if (krow >= d_pstart[4]) return;
    int srow = d_srow[krow];
    uint4 h;
    if (srow >= 0) {
        const float4* p = (const float4*)(emb + (size_t)srow * GTOT + cu * 8);
        float4 x0 = p[0], x1 = p[1];
        h.x = pack_h2(x0.x, x0.y); h.y = pack_h2(x0.z, x0.w);
        h.z = pack_h2(x1.x, x1.y); h.w = pack_h2(x1.z, x1.w);
    } else {
        h = make_uint4(0, 0, 0, 0);
    }
    *(uint4*)(d_Ge + (size_t)krow * GTOT + cu * 8) = h;
}

// ============================================================================
// Shared GEMM building blocks (BM=BN=128, BK=64, 256 threads, 8 warps 2Mx4N)
// 3-stage cp.async pipeline, ONE __syncthreads per K-iter.
// ============================================================================
__device__ __forceinline__ void load_tile64(uint32_t sDst, const __half* gBase,
                                            int rowStride, int kofs, int tid) {
#pragma unroll
    for (int i = 0; i < 4; i++) {
        int idx = tid + i * 256;            // 0..1023 -> 128 rows x 8 16B chunks
        int row = idx >> 3, cb = idx & 7;
        cp_async16(sDst + (uint32_t)(row * SROW + cb * 8) * 2u,
                   gBase + (size_t)row * rowStride + kofs + cb * 8);
    }
}

__device__ __forceinline__ void gemm_stage64(uint32_t sA, uint32_t sB, int wm, int wn,
                                             int lane, float (*c)[4][4]) {
#pragma unroll
    for (int ks = 0; ks < 4; ks++) {
        uint32_t a[4][4];
#pragma unroll
        for (int mt = 0; mt < 4; mt++) {
            int row = wm * 64 + mt * 16 + (lane & 15);
            int col = ks * 16 + ((lane >> 4) << 3);
            ldsm_x4(a[mt], sA + (uint32_t)(row * SROW + col) * 2u);
        }
#pragma unroll
        for (int g2 = 0; g2 < 2; g2++) {
            uint32_t b[4];
            int nrow = wn * 32 + g2 * 16 + (lane & 7) + ((lane >> 4) & 1) * 8;
            int col  = ks * 16 + ((lane >> 3) & 1) * 8;
            ldsm_x4(b, sB + (uint32_t)(nrow * SROW + col) * 2u);
#pragma unroll
            for (int mt = 0; mt < 4; mt++) {
                mma16816(c[mt][g2 * 2 + 0], a[mt], b[0], b[1]);
                mma16816(c[mt][g2 * 2 + 1], a[mt], b[2], b[3]);
            }
        }
    }
}

// 3-stage mainloop. Wait/sync/prefetch/commit ordering:
//   wait_group(1): with commits = kc+2 at iter kc, exactly stages 0..kc complete
//   sync: all warps done computing stage kc-1 -> buffer (kc+2)%3 is free
//   prefetch stage kc+2 (or commit an empty group to keep the count exact)
#define PIPE_LOOP(KT, LOADS)                                          \
    for (int kc = 0; kc < (KT); kc++) {                               \
        CP_WAIT(1);                                                   \
        __syncthreads();                                              \
        int nx = kc + 2;                                              \
        if (nx < (KT)) { int buf = nx - (nx >= 3 ? 3 : 0) - (nx >= 6 ? 3 : 0); \
                         int b3 = nx % 3; (void)buf;                  \
                         LOADS(b3, nx); }                             \
        CP_COMMIT();                                                  \
        gemm_stage64(sA[kc % 3], sB[kc % 3], wm, wn, lane, c);        \
    }

// ============================================================================
// Transition kernel: per (128-row unique tile, module-coltile) HMMA GEMM
//   delta[r,j] = sum_i g[r,i] * D[a][j,i];  g_next = clip(g + delta, -1, 1)
// grid.y jobs: 0,1 -> f0 col0/1; 2,3 -> f1 col0/1; 4 -> f2; 5 -> f3
// ============================================================================
__global__ void __launch_bounds__(256, 2) k_trans(float* __restrict__ outg) {
    extern __shared__ __align__(16) __half sm[];
    const int row0 = blockIdx.x * TILE_M;
    if (row0 >= d_pstart[4]) return;
    const int jy = blockIdx.y;
    const int f    = (jy < 2) ? 0 : (jy < 4) ? 1 : (jy == 4) ? 2 : 3;
    const int ct   = (jy == 1 || jy == 3) ? 1 : 0;
    const int n    = (f < 2) ? 256 : 128;
    const int koff = (f == 0) ? 0 : (f == 1) ? 256 : (f == 2) ? 512 : 640;
    const int moff = (f == 0) ? 0 : (f == 1) ? 262144 : (f == 2) ? 524288 : 589824;
    const int col0 = ct * 128;

    int a = 0;
    { int p1 = d_pstart[1], p2 = d_pstart[2], p3 = d_pstart[3];
      if (row0 >= p3) a = 3; else if (row0 >= p2) a = 2; else if (row0 >= p1) a = 1; }

    const int tid = threadIdx.x, lane = tid & 31, wid = tid >> 5;
    const int wm = wid & 1, wn = wid >> 1;
    uint32_t sb = smem_to_u32(sm);
    uint32_t sA[3] = { sb, sb + STAGE_B, sb + 2*STAGE_B };
    uint32_t sB[3] = { sb + 3*STAGE_B, sb + 4*STAGE_B, sb + 5*STAGE_B };

    const __half* Ab = d_Ge + (size_t)row0 * GTOT + koff;
    const __half* Bb = d_Dh + (size_t)moff + (size_t)a * n * n + (size_t)col0 * n;

    float c[4][4][4];
#pragma unroll
    for (int i = 0; i < 4; i++)
#pragma unroll
        for (int j = 0; j < 4; j++)
#pragma unroll
            for (int e = 0; e < 4; e++) c[i][j][e] = 0.0f;

    const int KT = n >> 6;      // 4 or 2
    load_tile64(sA[0], Ab, GTOT, 0, tid);
    load_tile64(sB[0], Bb, n,    0, tid);
    CP_COMMIT();
    load_tile64(sA[1], Ab, GTOT, 64, tid);
    load_tile64(sB[1], Bb, n,    64, tid);
    CP_COMMIT();
    for (int kc = 0; kc < KT; kc++) {
        CP_WAIT(1);
        __syncthreads();
        int nx = kc + 2;
        if (nx < KT) {
            int b3 = nx % 3;
            load_tile64(sA[b3], Ab, GTOT, nx * 64, tid);
            load_tile64(sB[b3], Bb, n,    nx * 64, tid);
        }
        CP_COMMIT();
        gemm_stage64(sA[kc % 3], sB[kc % 3], wm, wn, lane, c);
    }

    // epilogue: gn = clip(g + delta); fp16 to unique buf, fp32 fan-out to dup rows
#pragma unroll
    for (int mt = 0; mt < 4; mt++) {
#pragma unroll
        for (int e2 = 0; e2 < 2; e2++) {
            int krow = row0 + wm * 64 + mt * 16 + (lane >> 2) + e2 * 8;
            int cnt  = d_ucnt[krow];
            int roff = d_uroff[krow];
            int cbase = koff + col0 + wn * 32 + 2 * (lane & 3);
            const __half* gp = d_Ge + (size_t)krow * GTOT + cbase;
            __half*       hp = d_Gh + (size_t)krow * GTOT + cbase;
            float2 vals[4];
#pragma unroll
            for (int ng = 0; ng < 4; ng++) {
                __half2 g2v = *(const __half2*)(gp + ng * 8);
                float vx = __low2float(g2v)  + c[mt][ng][e2 * 2 + 0];
                float vy = __high2float(g2v) + c[mt][ng][e2 * 2 + 1];
                vx = fminf(1.0f, fmaxf(-1.0f, vx));
                vy = fminf(1.0f, fmaxf(-1.0f, vy));
                *(__half2*)(hp + ng * 8) = __floats2half2_rn(vx, vy);
                vals[ng].x = vx; vals[ng].y = vy;
            }
            for (int j = 0; j < cnt; j++) {
                int orow = d_rows[roff + j];
                float* op = outg + (size_t)orow * GTOT + cbase;
#pragma unroll
                for (int ng = 0; ng < 4; ng++)
                    *(float2*)(op + ng * 8) = vals[ng];
            }
        }
    }
}

// ============================================================================
// Classifier kernel: logits = g_next @ W^T + b   (128x128 tiles, K=768, BK=64)
// 256 threads, 2 CTAs/SM, 3-stage pipeline
// ============================================================================
__global__ void __launch_bounds__(256, 2) k_cls(const float* __restrict__ bias,
                                                float* __restrict__ out) {
    extern __shared__ __align__(16) __half sm[];
    const int row0 = blockIdx.x * TILE_M;
    if (row0 >= d_pstart[4]) return;
    const int col0 = blockIdx.y * 128;

    const int tid = threadIdx.x, lane = tid & 31, wid = tid >> 5;
    const int wm = wid & 1, wn = wid >> 1;
    uint32_t sb = smem_to_u32(sm);
    uint32_t sA[3] = { sb, sb + STAGE_B, sb + 2*STAGE_B };
    uint32_t sB[3] = { sb + 3*STAGE_B, sb + 4*STAGE_B, sb + 5*STAGE_B };

    const __half* Ab = d_Gh + (size_t)row0 * GTOT;
    const __half* Bb = d_Wh + (size_t)col0 * GTOT;

    float c[4][4][4];
#pragma unroll
    for (int i = 0; i < 4; i++)
#pragma unroll
        for (int j = 0; j < 4; j++)
#pragma unroll
            for (int e = 0; e < 4; e++) c[i][j][e] = 0.0f;

    const int KT = GTOT >> 6;   // 12
    load_tile64(sA[0], Ab, GTOT, 0, tid);
    load_tile64(sB[0], Bb, GTOT, 0, tid);
    CP_COMMIT();
    load_tile64(sA[1], Ab, GTOT, 64, tid);
    load_tile64(sB[1], Bb, GTOT, 64, tid);
    CP_COMMIT();
    for (int kc = 0; kc < KT; kc++) {
        CP_WAIT(1);
        __syncthreads();
        int nx = kc + 2;
        if (nx < KT) {
            int b3 = nx % 3;
            load_tile64(sA[b3], Ab, GTOT, nx * 64, tid);
            load_tile64(sB[b3], Bb, GTOT, nx * 64, tid);
        }
        CP_COMMIT();
        gemm_stage64(sA[kc % 3], sB[kc % 3], wm, wn, lane, c);
    }

    // epilogue: add bias, fan logits out to all duplicate original rows
#pragma unroll
    for (int mt = 0; mt < 4; mt++) {
#pragma unroll
        for (int e2 = 0; e2 < 2; e2++) {
            int krow = row0 + wm * 64 + mt * 16 + (lane >> 2) + e2 * 8;
            int cnt  = d_ucnt[krow];
            if (cnt == 0) continue;
            int roff = d_uroff[krow];
            int cbase = col0 + wn * 32 + 2 * (lane & 3);
            float2 vals[4];
#pragma unroll
            for (int ng = 0; ng < 4; ng++) {
                float2 bv = *(const float2*)(bias + cbase + ng * 8);
                vals[ng].x = c[mt][ng][e2 * 2 + 0] + bv.x;
                vals[ng].y = c[mt][ng][e2 * 2 + 1] + bv.y;
            }
            for (int j = 0; j < cnt; j++) {
                int orow = d_rows[roff + j];
                float* op = out + (size_t)orow * NSTATES + cbase;
#pragma unroll
                for (int ng = 0; ng < 4; ng++)
                    *(float2*)(op + ng * 8) = vals[ng];
            }
        }
    }
}

// ============================================================================
// Host launch (graph-capturable: kernel launches only)
// ============================================================================
extern "C" void kernel_launch(void* const* d_in, const int* in_sizes, int n_in,
                              void* d_out, int out_size) {
    // Identify inputs by element count (unambiguous for this problem):
    //   16384 (x2): current_state_index, action_index   (metadata order: state first)
    //   3145728 (x2): emb, W_cls      4096: b_cls
    //   262144 (x2): D0, D1           65536 (x2): D2, D3
    const int *state = nullptr, *act = nullptr;
    const float *emb = nullptr, *W = nullptr, *bias = nullptr;
    const float *D0 = nullptr, *D1 = nullptr, *D2 = nullptr, *D3 = nullptr;
    for (int i = 0; i < n_in; i++) {
        int s = in_sizes[i];
        const void* p = d_in[i];
        if      (s == 16384)   { if (!state) state = (const int*)p; else act = (const int*)p; }
        else if (s == 3145728) { if (!emb)   emb   = (const float*)p; else W = (const float*)p; }
        else if (s == 4096)    { bias = (const float*)p; }
        else if (s == 262144)  { if (!D0) D0 = (const float*)p; else D1 = (const float*)p; }
        else if (s == 65536)   { if (!D2) D2 = (const float*)p; else D3 = (const float*)p; }
    }

    float* out  = (float*)d_out;                       // logits [16384, 4096]
    float* outg = out + (size_t)B_TOTAL * NSTATES;     // g_next [16384, 768]

    cudaFuncSetAttribute(k_trans, cudaFuncAttributeMaxDynamicSharedMemorySize, SMEM_P);
    cudaFuncSetAttribute(k_cls,   cudaFuncAttributeMaxDynamicSharedMemorySize, SMEM_P);

    k_conv<<<512, 256>>>(W, D0, D1, D2, D3);
    k_zero<<<(P_MAX + 255) / 256, 256>>>();
    k_hist<<<64, 256>>>(act, state);
    k_scanA<<<SCAN_BLKS, 256>>>();
    k_scanB<<<SCAN_BLKS, 256>>>();
    k_scatter<<<64, 256>>>(act, state);
    k_gather<<<P_MAX * (GTOT / 8) / 256, 256>>>(emb);
    k_trans<<<dim3(MAX_TILES, 6), 256, SMEM_P>>>(outg);
    k_cls<<<dim3(MAX_TILES, 32), 256, SMEM_P>>>(bias, out);
}

// round 14
// speedup vs baseline: 1.5504x; 1.0218x over previous
#include <cuda_runtime.h>
#include <cuda_fp16.h>
#include <cstdint>

// ============================================================================
// Problem constants
// ============================================================================
#define B_TOTAL   16384
#define NSTATES   4096
#define N_ACT     4
#define NKEYS     (NSTATES*N_ACT)     // 16384 (action*4096 + state)
#define GTOT      768
#define TILE_M    128
#define MAX_TILES 132                 // worst case: all pairs unique + per-action pad
#define P_MAX     (MAX_TILES*TILE_M)  // 16896
#define NW        (NSTATES*GTOT)      // 3145728
#define ND        655360              // 4*(256^2+256^2+128^2+128^2)

// smem tile: 128 rows x 64 halves, padded row stride 72 halves (144B).
// 144 mod 128 = 16 -> 8 consecutive rows land on 8 distinct 16B banks: conflict-free ldmatrix.
#define SROW      72
#define STAGE_H   (128*SROW)          // halves per operand tile (9216)
#define STAGE_B   (STAGE_H*2)         // bytes per operand tile (18432)
#define SMEM_P    (6*STAGE_B)         // 3-stage pipeline: A0..A2 B0..B2 = 110592 B

#define SCAN_BLKS 16                  // 1024 keys per block; 4 blocks per action

// ============================================================================
// PTX helpers (baseline sm_80+ features only — target is compute_103 non-'a')
// ============================================================================
__device__ __forceinline__ uint32_t smem_to_u32(const void* smem_ptr) {
    uint32_t addr;
    asm("{ .reg .u64 tmp; cvta.to.shared.u64 tmp, %1; cvt.u32.u64 %0, tmp; }"
        : "=r"(addr) : "l"(smem_ptr));
    return addr;
}
__device__ __forceinline__ void cp_async16(uint32_t s, const void* g) {
    asm volatile("cp.async.cg.shared.global [%0], [%1], 16;" :: "r"(s), "l"(g));
}
#define CP_COMMIT() asm volatile("cp.async.commit_group;" ::: "memory")
#define CP_WAIT(n)  asm volatile("cp.async.wait_group %0;" :: "n"(n) : "memory")

__device__ __forceinline__ void ldsm_x4(uint32_t* r, uint32_t addr) {
    asm volatile("ldmatrix.sync.aligned.m8n8.x4.shared.b16 {%0,%1,%2,%3}, [%4];"
        : "=r"(r[0]), "=r"(r[1]), "=r"(r[2]), "=r"(r[3]) : "r"(addr));
}
__device__ __forceinline__ void mma16816(float* c, const uint32_t* a,
                                         uint32_t b0, uint32_t b1) {
    asm volatile(
        "mma.sync.aligned.m16n8k16.row.col.f32.f16.f16.f32 "
        "{%0,%1,%2,%3}, {%4,%5,%6,%7}, {%8,%9}, {%0,%1,%2,%3};"
        : "+f"(c[0]), "+f"(c[1]), "+f"(c[2]), "+f"(c[3])
        : "r"(a[0]), "r"(a[1]), "r"(a[2]), "r"(a[3]), "r"(b0), "r"(b1));
}
__device__ __forceinline__ uint32_t pack_h2(float a, float b) {
    __half2 h = __floats2half2_rn(a, b);
    return *reinterpret_cast<uint32_t*>(&h);
}
// evict-first streaming store (output is never re-read; keep L2 for operands)
__device__ __forceinline__ void st_cs_f2(float* p, float2 v) {
    asm volatile("st.global.cs.v2.f32 [%0], {%1, %2};" :: "l"(p), "f"(v.x), "f"(v.y) : "memory");
}

// ============================================================================
// Device scratch (static globals — no runtime allocation)
// ============================================================================
__device__ __align__(128) __half d_Wh[NW];                       // W_cls fp16
__device__ __align__(128) __half d_Dh[ND];                       // D banks fp16
__device__ __align__(128) __half d_Ge[(size_t)P_MAX * GTOT];     // gathered emb (unique) fp16
__device__ __align__(128) __half d_Gh[(size_t)P_MAX * GTOT];     // g_next (unique) fp16

__device__ __align__(16) int d_hist[NKEYS];  // key -> multiplicity
__device__ int d_cur[NKEYS];        // scatter cursor per key
__device__ int d_roff[NKEYS];       // key -> offset into d_rows
__device__ int d_rows[B_TOTAL];     // original row ids, grouped by key
__device__ int d_srow[P_MAX];       // unique slot -> state (-1 pad)
__device__ int d_uroff[P_MAX];      // unique slot -> offset into d_rows
__device__ int d_ucnt[P_MAX];       // unique slot -> multiplicity (0 pad)
__device__ int d_pstart[5];         // 128-aligned padded per-action starts, [4]=total
__device__ int d_bU[SCAN_BLKS];     // per-scan-block unique count
__device__ int d_bT[SCAN_BLKS];     // per-scan-block total count

// ============================================================================
// Pre-pass: convert fp32->fp16 (+ fused zero/init); key histogram; scan;
// scatter; gather
// ============================================================================
__global__ void k_conv(const float* __restrict__ W,
                       const float* __restrict__ D0, const float* __restrict__ D1,
                       const float* __restrict__ D2, const float* __restrict__ D3) {
    int gid = blockIdx.x * blockDim.x + threadIdx.x;
    // fused zero/init (grid has 131072 threads >= NKEYS, P_MAX)
    if (gid < NKEYS) { d_hist[gid] = 0; d_cur[gid] = 0; }
    if (gid < P_MAX) { d_srow[gid] = -1; d_ucnt[gid] = 0; d_uroff[gid] = 0; }
    const int total = NW + ND;
    for (int i = gid; i < total; i += gridDim.x * blockDim.x) {
        if (i < NW) {
            d_Wh[i] = __float2half_rn(W[i]);
        } else {
            int j = i - NW;
            const float* src; int o;
            if      (j < 262144) { src = D0; o = j; }
            else if (j < 524288) { src = D1; o = j - 262144; }
            else if (j < 589824) { src = D2; o = j - 524288; }
            else                 { src = D3; o = j - 589824; }
            d_Dh[j] = __float2half_rn(src[o]);
        }
    }
}

__global__ void k_hist(const int* __restrict__ act, const int* __restrict__ state) {
    int i = blockIdx.x * 256 + threadIdx.x;
    int key = act[i] * NSTATES + state[i];
    atomicAdd(&d_hist[key], 1);
}

// Phase A: 16 blocks x 256 threads, 4 keys/thread -> per-block {unique, total} sums
__global__ void k_scanA() {
    __shared__ int sU[8], sT[8];
    const int t = threadIdx.x, lane = t & 31, warp = t >> 5;
    const int k0 = (blockIdx.x * 256 + t) * 4;
    int4 x = *(const int4*)(d_hist + k0);
    int nu = (x.x != 0) + (x.y != 0) + (x.z != 0) + (x.w != 0);
    int nt = x.x + x.y + x.z + x.w;
#pragma unroll
    for (int o = 16; o > 0; o >>= 1) {
        nu += __shfl_down_sync(~0u, nu, o);
        nt += __shfl_down_sync(~0u, nt, o);
    }
    if (lane == 0) { sU[warp] = nu; sT[warp] = nt; }
    __syncthreads();
    if (t == 0) {
        int tu = 0, tt = 0;
#pragma unroll
        for (int w = 0; w < 8; w++) { tu += sU[w]; tt += sT[w]; }
        d_bU[blockIdx.x] = tu;
        d_bT[blockIdx.x] = tt;
    }
}

// Phase B: 16 blocks; each recomputes the 16-entry prefix, scans its 1024 keys, writes.
__global__ void k_scanB() {
    __shared__ int wU[8], wT[8];
    __shared__ int base_u, base_r, pstS[5];
    const int t = threadIdx.x, lane = t & 31, warp = t >> 5;
    const int blk = blockIdx.x;

    if (t == 0) {
        int bU[SCAN_BLKS], bT[SCAN_BLKS];
#pragma unroll
        for (int b = 0; b < SCAN_BLKS; b++) { bU[b] = d_bU[b]; bT[b] = d_bT[b]; }
        int p = 0;
#pragma unroll
        for (int a = 0; a < N_ACT; a++) {
            pstS[a] = p;
            int ua = bU[a * 4] + bU[a * 4 + 1] + bU[a * 4 + 2] + bU[a * 4 + 3];
            p += ((ua + TILE_M - 1) / TILE_M) * TILE_M;
        }
        pstS[4] = p;
        if (blk == 0) {
#pragma unroll
            for (int a = 0; a <= N_ACT; a++) d_pstart[a] = pstS[a];
        }
        int a = blk >> 2;
        int u = pstS[a];
        for (int b = a * 4; b < blk; b++) u += bU[b];
        int r = 0;
        for (int b = 0; b < blk; b++) r += bT[b];
        base_u = u; base_r = r;
    }
    __syncthreads();

    const int k0 = (blk * 256 + t) * 4;
    int4 x = *(const int4*)(d_hist + k0);
    int h[4] = { x.x, x.y, x.z, x.w };
    int nu = (h[0] != 0) + (h[1] != 0) + (h[2] != 0) + (h[3] != 0);
    int nt = h[0] + h[1] + h[2] + h[3];
    int su = nu, st = nt;
#pragma unroll
    for (int o = 1; o < 32; o <<= 1) {
        int vu = __shfl_up_sync(~0u, su, o);
        int vt = __shfl_up_sync(~0u, st, o);
        if (lane >= o) { su += vu; st += vt; }
    }
    if (lane == 31) { wU[warp] = su; wT[warp] = st; }
    __syncthreads();
    int wexU = 0, wexT = 0;
    for (int w = 0; w < warp; w++) { wexU += wU[w]; wexT += wT[w]; }
    int u = base_u + wexU + (su - nu);
    int r = base_r + wexT + (st - nt);
#pragma unroll
    for (int i = 0; i < 4; i++) {
        int k = k0 + i;
        if (h[i]) {
            d_roff[k] = r;
            d_srow[u] = k & (NSTATES - 1);
            d_uroff[u] = r; d_ucnt[u] = h[i];
            u++; r += h[i];
        }
    }
}

__global__ void k_scatter(const int* __restrict__ act, const int* __restrict__ state) {
    int i = blockIdx.x * 256 + threadIdx.x;
    int key = act[i] * NSTATES + state[i];
    int pos = atomicAdd(&d_cur[key], 1);
    d_rows[d_roff[key] + pos] = i;
}

// gather emb rows into unique fp16 buffer d_Ge (zeros for pad rows)
__global__ void k_gather(const float* __restrict__ emb) {
    int i = blockIdx.x * 256 + threadIdx.x;     // one uint4 (8 halves) per thread
    int krow = i / (GTOT / 8);
    int cu   = i - krow * (GTOT / 8);
    if (krow >= d_pstart[4]) return;
    int srow = d_srow[krow];
    uint4 h;
    if (srow >= 0) {
        const float4* p = (const float4*)(emb + (size_t)srow * GTOT + cu * 8);
        float4 x0 = p[0], x1 = p[1];
        h.x = pack_h2(x0.x, x0.y); h.y = pack_h2(x0.z, x0.w);
        h.z = pack_h2(x1.x, x1.y); h.w = pack_h2(x1.z, x1.w);
    } else {
        h = make_uint4(0, 0, 0, 0);
    }
    *(uint4*)(d_Ge + (size_t)krow * GTOT + cu * 8) = h;
}

// ============================================================================
// Shared GEMM building blocks (BM=BN=128, BK=64, 256 threads, 8 warps 2Mx4N)
// 3-stage cp.async pipeline, ONE __syncthreads per K-iter.
// ============================================================================
__device__ __forceinline__ void load_tile64(uint32_t sDst, const __half* gBase,
                                            int rowStride, int kofs, int tid) {
#pragma unroll
    for (int i = 0; i < 4; i++) {
        int idx = tid + i * 256;            // 0..1023 -> 128 rows x 8 16B chunks
        int row = idx >> 3, cb = idx & 7;
        cp_async16(sDst + (uint32_t)(row * SROW + cb * 8) * 2u,
                   gBase + (size_t)row * rowStride + kofs + cb * 8);
    }
}

__device__ __forceinline__ void gemm_stage64(uint32_t sA, uint32_t sB, int wm, int wn,
                                             int lane, float (*c)[4][4]) {
#pragma unroll
    for (int ks = 0; ks < 4; ks++) {
        uint32_t a[4][4];
#pragma unroll
        for (int mt = 0; mt < 4; mt++) {
            int row = wm * 64 + mt * 16 + (lane & 15);
            int col = ks * 16 + ((lane >> 4) << 3);
            ldsm_x4(a[mt], sA + (uint32_t)(row * SROW + col) * 2u);
        }
#pragma unroll
        for (int g2 = 0; g2 < 2; g2++) {
            uint32_t b[4];
            int nrow = wn * 32 + g2 * 16 + (lane & 7) + ((lane >> 4) & 1) * 8;
            int col  = ks * 16 + ((lane >> 3) & 1) * 8;
            ldsm_x4(b, sB + (uint32_t)(nrow * SROW + col) * 2u);
#pragma unroll
            for (int mt = 0; mt < 4; mt++) {
                mma16816(c[mt][g2 * 2 + 0], a[mt], b[0], b[1]);
                mma16816(c[mt][g2 * 2 + 1], a[mt], b[2], b[3]);
            }
        }
    }
}

// ============================================================================
// Transition kernel: per (128-row unique tile, module-coltile) HMMA GEMM
//   delta[r,j] = sum_i g[r,i] * D[a][j,i];  g_next = clip(g + delta, -1, 1)
// grid.y jobs: 0,1 -> f0 col0/1; 2,3 -> f1 col0/1; 4 -> f2; 5 -> f3
// ============================================================================
__global__ void __launch_bounds__(256, 2) k_trans(float* __restrict__ outg) {
    extern __shared__ __align__(16) __half sm[];
    const int row0 = blockIdx.x * TILE_M;
    if (row0 >= d_pstart[4]) return;
    const int jy = blockIdx.y;
    const int f    = (jy < 2) ? 0 : (jy < 4) ? 1 : (jy == 4) ? 2 : 3;
    const int ct   = (jy == 1 || jy == 3) ? 1 : 0;
    const int n    = (f < 2) ? 256 : 128;
    const int koff = (f == 0) ? 0 : (f == 1) ? 256 : (f == 2) ? 512 : 640;
    const int moff = (f == 0) ? 0 : (f == 1) ? 262144 : (f == 2) ? 524288 : 589824;
    const int col0 = ct * 128;

    int a = 0;
    { int p1 = d_pstart[1], p2 = d_pstart[2], p3 = d_pstart[3];
      if (row0 >= p3) a = 3; else if (row0 >= p2) a = 2; else if (row0 >= p1) a = 1; }

    const int tid = threadIdx.x, lane = tid & 31, wid = tid >> 5;
    const int wm = wid & 1, wn = wid >> 1;
    uint32_t sb = smem_to_u32(sm);
    uint32_t sA[3] = { sb, sb + STAGE_B, sb + 2*STAGE_B };
    uint32_t sB[3] = { sb + 3*STAGE_B, sb + 4*STAGE_B, sb + 5*STAGE_B };

    const __half* Ab = d_Ge + (size_t)row0 * GTOT + koff;
    const __half* Bb = d_Dh + (size_t)moff + (size_t)a * n * n + (size_t)col0 * n;

    float c[4][4][4];
#pragma unroll
    for (int i = 0; i < 4; i++)
#pragma unroll
        for (int j = 0; j < 4; j++)
#pragma unroll
            for (int e = 0; e < 4; e++) c[i][j][e] = 0.0f;

    const int KT = n >> 6;      // 4 or 2
    load_tile64(sA[0], Ab, GTOT, 0, tid);
    load_tile64(sB[0], Bb, n,    0, tid);
    CP_COMMIT();
    load_tile64(sA[1], Ab, GTOT, 64, tid);
    load_tile64(sB[1], Bb, n,    64, tid);
    CP_COMMIT();
    for (int kc = 0; kc < KT; kc++) {
        CP_WAIT(1);
        __syncthreads();
        int nx = kc + 2;
        if (nx < KT) {
            int b3 = nx % 3;
            load_tile64(sA[b3], Ab, GTOT, nx * 64, tid);
            load_tile64(sB[b3], Bb, n,    nx * 64, tid);
        }
        CP_COMMIT();
        gemm_stage64(sA[kc % 3], sB[kc % 3], wm, wn, lane, c);
    }

    // epilogue: gn = clip(g + delta); fp16 to unique buf, fp32 fan-out to dup rows
#pragma unroll
    for (int mt = 0; mt < 4; mt++) {
#pragma unroll
        for (int e2 = 0; e2 < 2; e2++) {
            int krow = row0 + wm * 64 + mt * 16 + (lane >> 2) + e2 * 8;
            int cnt  = d_ucnt[krow];
            int roff = d_uroff[krow];
            int cbase = koff + col0 + wn * 32 + 2 * (lane & 3);
            const __half* gp = d_Ge + (size_t)krow * GTOT + cbase;
            __half*       hp = d_Gh + (size_t)krow * GTOT + cbase;
            float2 vals[4];
#pragma unroll
            for (int ng = 0; ng < 4; ng++) {
                __half2 g2v = *(const __half2*)(gp + ng * 8);
                float vx = __low2float(g2v)  + c[mt][ng][e2 * 2 + 0];
                float vy = __high2float(g2v) + c[mt][ng][e2 * 2 + 1];
                vx = fminf(1.0f, fmaxf(-1.0f, vx));
                vy = fminf(1.0f, fmaxf(-1.0f, vy));
                *(__half2*)(hp + ng * 8) = __floats2half2_rn(vx, vy);
                vals[ng].x = vx; vals[ng].y = vy;
            }
            for (int j = 0; j < cnt; j++) {
                int orow = d_rows[roff + j];
                float* op = outg + (size_t)orow * GTOT + cbase;
#pragma unroll
                for (int ng = 0; ng < 4; ng++)
                    st_cs_f2(op + ng * 8, vals[ng]);
            }
        }
    }
}

// ============================================================================
// Classifier kernel: logits = g_next @ W^T + b   (128x128 tiles, K=768, BK=64)
// 256 threads, 2 CTAs/SM, 3-stage pipeline
// ============================================================================
__global__ void __launch_bounds__(256, 2) k_cls(const float* __restrict__ bias,
                                                float* __restrict__ out) {
    extern __shared__ __align__(16) __half sm[];
    const int row0 = blockIdx.x * TILE_M;
    if (row0 >= d_pstart[4]) return;
    const int col0 = blockIdx.y * 128;

    const int tid = threadIdx.x, lane = tid & 31, wid = tid >> 5;
    const int wm = wid & 1, wn = wid >> 1;
    uint32_t sb = smem_to_u32(sm);
    uint32_t sA[3] = { sb, sb + STAGE_B, sb + 2*STAGE_B };
    uint32_t sB[3] = { sb + 3*STAGE_B, sb + 4*STAGE_B, sb + 5*STAGE_B };

    const __half* Ab = d_Gh + (size_t)row0 * GTOT;
    const __half* Bb = d_Wh + (size_t)col0 * GTOT;

    float c[4][4][4];
#pragma unroll
    for (int i = 0; i < 4; i++)
#pragma unroll
        for (int j = 0; j < 4; j++)
#pragma unroll
            for (int e = 0; e < 4; e++) c[i][j][e] = 0.0f;

    const int KT = GTOT >> 6;   // 12
    load_tile64(sA[0], Ab, GTOT, 0, tid);
    load_tile64(sB[0], Bb, GTOT, 0, tid);
    CP_COMMIT();
    load_tile64(sA[1], Ab, GTOT, 64, tid);
    load_tile64(sB[1], Bb, GTOT, 64, tid);
    CP_COMMIT();
    for (int kc = 0; kc < KT; kc++) {
        CP_WAIT(1);
        __syncthreads();
        int nx = kc + 2;
        if (nx < KT) {
            int b3 = nx % 3;
            load_tile64(sA[b3], Ab, GTOT, nx * 64, tid);
            load_tile64(sB[b3], Bb, GTOT, nx * 64, tid);
        }
        CP_COMMIT();
        gemm_stage64(sA[kc % 3], sB[kc % 3], wm, wn, lane, c);
    }

    // epilogue: add bias, fan logits out to all duplicate original rows
#pragma unroll
    for (int mt = 0; mt < 4; mt++) {
#pragma unroll
        for (int e2 = 0; e2 < 2; e2++) {
            int krow = row0 + wm * 64 + mt * 16 + (lane >> 2) + e2 * 8;
            int cnt  = d_ucnt[krow];
            if (cnt == 0) continue;
            int roff = d_uroff[krow];
            int cbase = col0 + wn * 32 + 2 * (lane & 3);
            float2 vals[4];
#pragma unroll
            for (int ng = 0; ng < 4; ng++) {
                float2 bv = *(const float2*)(bias + cbase + ng * 8);
                vals[ng].x = c[mt][ng][e2 * 2 + 0] + bv.x;
                vals[ng].y = c[mt][ng][e2 * 2 + 1] + bv.y;
            }
            for (int j = 0; j < cnt; j++) {
                int orow = d_rows[roff + j];
                float* op = out + (size_t)orow * NSTATES + cbase;
#pragma unroll
                for (int ng = 0; ng < 4; ng++)
                    st_cs_f2(op + ng * 8, vals[ng]);
            }
        }
    }
}

// ============================================================================
// Host launch (graph-capturable: kernel launches only)
// ============================================================================
extern "C" void kernel_launch(void* const* d_in, const int* in_sizes, int n_in,
                              void* d_out, int out_size) {
    // Identify inputs by element count (unambiguous for this problem):
    //   16384 (x2): current_state_index, action_index   (metadata order: state first)
    //   3145728 (x2): emb, W_cls      4096: b_cls
    //   262144 (x2): D0, D1           65536 (x2): D2, D3
    const int *state = nullptr, *act = nullptr;
    const float *emb = nullptr, *W = nullptr, *bias = nullptr;
    const float *D0 = nullptr, *D1 = nullptr, *D2 = nullptr, *D3 = nullptr;
    for (int i = 0; i < n_in; i++) {
        int s = in_sizes[i];
        const void* p = d_in[i];
        if      (s == 16384)   { if (!state) state = (const int*)p; else act = (const int*)p; }
        else if (s == 3145728) { if (!emb)   emb   = (const float*)p; else W = (const float*)p; }
        else if (s == 4096)    { bias = (const float*)p; }
        else if (s == 262144)  { if (!D0) D0 = (const float*)p; else D1 = (const float*)p; }
        else if (s == 65536)   { if (!D2) D2 = (const float*)p; else D3 = (const float*)p; }
    }

    float* out  = (float*)d_out;                       // logits [16384, 4096]
    float* outg = out + (size_t)B_TOTAL * NSTATES;     // g_next [16384, 768]

    cudaFuncSetAttribute(k_trans, cudaFuncAttributeMaxDynamicSharedMemorySize, SMEM_P);
    cudaFuncSetAttribute(k_cls,   cudaFuncAttributeMaxDynamicSharedMemorySize, SMEM_P);

    k_conv<<<512, 256>>>(W, D0, D1, D2, D3);   // + fused zero/init
    k_hist<<<64, 256>>>(act, state);
    k_scanA<<<SCAN_BLKS, 256>>>();
    k_scanB<<<SCAN_BLKS, 256>>>();
    k_scatter<<<64, 256>>>(act, state);
    k_gather<<<P_MAX * (GTOT / 8) / 256, 256>>>(emb);
    k_trans<<<dim3(MAX_TILES, 6), 256, SMEM_P>>>(outg);
    k_cls<<<dim3(MAX_TILES, 32), 256, SMEM_P>>>(bias, out);
}

// round 15
// speedup vs baseline: 1.6125x; 1.0401x over previous
#include <cuda_runtime.h>
#include <cuda_fp16.h>
#include <cstdint>

// ============================================================================
// Problem constants
// ============================================================================
#define B_TOTAL   16384
#define NSTATES   4096
#define N_ACT     4
#define NKEYS     (NSTATES*N_ACT)     // 16384 (action*4096 + state)
#define GTOT      768
#define TILE_M    128
#define MAX_TILES 132                 // worst case: all pairs unique + per-action pad
#define P_MAX     (MAX_TILES*TILE_M)  // 16896
#define NW        (NSTATES*GTOT)      // 3145728
#define ND        655360              // 4*(256^2+256^2+128^2+128^2)

// smem tile: 128 rows x 64 halves, padded row stride 72 halves (144B).
// 144 mod 128 = 16 -> 8 consecutive rows land on 8 distinct 16B banks: conflict-free ldmatrix.
#define SROW      72
#define STAGE_H   (128*SROW)          // halves per operand tile (9216)
#define STAGE_B   (STAGE_H*2)         // bytes per operand tile (18432)
#define SMEM_P    (6*STAGE_B)         // 3-stage pipeline: A0..A2 B0..B2 = 110592 B

#define SCAN_BLKS 16                  // 1024 keys per block; 4 blocks per action

// ============================================================================
// PTX helpers (baseline sm_80+ features only — target is compute_103 non-'a')
// ============================================================================
__device__ __forceinline__ uint32_t smem_to_u32(const void* smem_ptr) {
    uint32_t addr;
    asm("{ .reg .u64 tmp; cvta.to.shared.u64 tmp, %1; cvt.u32.u64 %0, tmp; }"
        : "=r"(addr) : "l"(smem_ptr));
    return addr;
}
__device__ __forceinline__ void cp_async16(uint32_t s, const void* g) {
    asm volatile("cp.async.cg.shared.global [%0], [%1], 16;" :: "r"(s), "l"(g));
}
#define CP_COMMIT() asm volatile("cp.async.commit_group;" ::: "memory")
#define CP_WAIT(n)  asm volatile("cp.async.wait_group %0;" :: "n"(n) : "memory")

__device__ __forceinline__ void ldsm_x4(uint32_t* r, uint32_t addr) {
    asm volatile("ldmatrix.sync.aligned.m8n8.x4.shared.b16 {%0,%1,%2,%3}, [%4];"
        : "=r"(r[0]), "=r"(r[1]), "=r"(r[2]), "=r"(r[3]) : "r"(addr));
}
__device__ __forceinline__ void mma16816(float* c, const uint32_t* a,
                                         uint32_t b0, uint32_t b1) {
    asm volatile(
        "mma.sync.aligned.m16n8k16.row.col.f32.f16.f16.f32 "
        "{%0,%1,%2,%3}, {%4,%5,%6,%7}, {%8,%9}, {%0,%1,%2,%3};"
        : "+f"(c[0]), "+f"(c[1]), "+f"(c[2]), "+f"(c[3])
        : "r"(a[0]), "r"(a[1]), "r"(a[2]), "r"(a[3]), "r"(b0), "r"(b1));
}
__device__ __forceinline__ uint32_t pack_h2(float a, float b) {
    __half2 h = __floats2half2_rn(a, b);
    return *reinterpret_cast<uint32_t*>(&h);
}
// evict-first streaming store (output is never re-read; keep L2 for operands)
__device__ __forceinline__ void st_cs_f2(float* p, float2 v) {
    asm volatile("st.global.cs.v2.f32 [%0], {%1, %2};" :: "l"(p), "f"(v.x), "f"(v.y) : "memory");
}
__device__ __forceinline__ uint2 cvt4(float4 x) {
    __half2 h0 = __floats2half2_rn(x.x, x.y);
    __half2 h1 = __floats2half2_rn(x.z, x.w);
    uint2 v;
    v.x = *reinterpret_cast<uint32_t*>(&h0);
    v.y = *reinterpret_cast<uint32_t*>(&h1);
    return v;
}

// ============================================================================
// Device scratch (static globals — no runtime allocation)
// ============================================================================
__device__ __align__(128) __half d_Wh[NW];                       // W_cls fp16
__device__ __align__(128) __half d_Dh[ND];                       // D banks fp16
__device__ __align__(128) __half d_Ge[(size_t)P_MAX * GTOT];     // gathered emb (unique) fp16
__device__ __align__(128) __half d_Gh[(size_t)P_MAX * GTOT];     // g_next (unique) fp16

__device__ __align__(16) int d_hist[NKEYS];  // key -> multiplicity
__device__ int d_cur[NKEYS];        // scatter cursor per key
__device__ int d_roff[NKEYS];       // key -> offset into d_rows
__device__ int d_rows[B_TOTAL];     // original row ids, grouped by key
__device__ int d_srow[P_MAX];       // unique slot -> state (-1 pad)
__device__ int d_uroff[P_MAX];      // unique slot -> offset into d_rows
__device__ int d_ucnt[P_MAX];       // unique slot -> multiplicity (0 pad)
__device__ int d_pstart[5];         // 128-aligned padded per-action starts, [4]=total
__device__ int d_bU[SCAN_BLKS];     // per-scan-block unique count
__device__ int d_bT[SCAN_BLKS];     // per-scan-block total count

// ============================================================================
// Pre-pass kernels
// ============================================================================
// zero/init + D-bank convert (vectorized). grid = 640 x 256 = 163840 threads,
// exactly ND/4 float4 conversions; boundaries all divisible by 4.
__global__ void k_init(const float* __restrict__ D0, const float* __restrict__ D1,
                       const float* __restrict__ D2, const float* __restrict__ D3) {
    int gid = blockIdx.x * 256 + threadIdx.x;
    if (gid < NKEYS) { d_hist[gid] = 0; d_cur[gid] = 0; }
    if (gid < P_MAX) { d_srow[gid] = -1; d_ucnt[gid] = 0; d_uroff[gid] = 0; }
    int j = gid * 4;
    const float* src; int o;
    if      (j < 262144) { src = D0; o = j; }
    else if (j < 524288) { src = D1; o = j - 262144; }
    else if (j < 589824) { src = D2; o = j - 524288; }
    else                 { src = D3; o = j - 589824; }
    float4 x = *(const float4*)(src + o);
    *(uint2*)(d_Dh + j) = cvt4(x);
}

// W convert (vectorized), runs on a forked stream overlapped with the sort chain.
// grid = 3072 x 256 = 786432 threads = NW/4.
__global__ void k_convW(const float* __restrict__ W) {
    int j = (blockIdx.x * 256 + threadIdx.x) * 4;
    float4 x = *(const float4*)(W + j);
    *(uint2*)(d_Wh + j) = cvt4(x);
}

__global__ void k_hist(const int* __restrict__ act, const int* __restrict__ state) {
    int i = blockIdx.x * 256 + threadIdx.x;
    int key = act[i] * NSTATES + state[i];
    atomicAdd(&d_hist[key], 1);
}

// Phase A: 16 blocks x 256 threads, 4 keys/thread -> per-block {unique, total} sums
__global__ void k_scanA() {
    __shared__ int sU[8], sT[8];
    const int t = threadIdx.x, lane = t & 31, warp = t >> 5;
    const int k0 = (blockIdx.x * 256 + t) * 4;
    int4 x = *(const int4*)(d_hist + k0);
    int nu = (x.x != 0) + (x.y != 0) + (x.z != 0) + (x.w != 0);
    int nt = x.x + x.y + x.z + x.w;
#pragma unroll
    for (int o = 16; o > 0; o >>= 1) {
        nu += __shfl_down_sync(~0u, nu, o);
        nt += __shfl_down_sync(~0u, nt, o);
    }
    if (lane == 0) { sU[warp] = nu; sT[warp] = nt; }
    __syncthreads();
    if (t == 0) {
        int tu = 0, tt = 0;
#pragma unroll
        for (int w = 0; w < 8; w++) { tu += sU[w]; tt += sT[w]; }
        d_bU[blockIdx.x] = tu;
        d_bT[blockIdx.x] = tt;
    }
}

// Phase B: 16 blocks; each recomputes the 16-entry prefix, scans its 1024 keys, writes.
__global__ void k_scanB() {
    __shared__ int wU[8], wT[8];
    __shared__ int base_u, base_r, pstS[5];
    const int t = threadIdx.x, lane = t & 31, warp = t >> 5;
    const int blk = blockIdx.x;

    if (t == 0) {
        int bU[SCAN_BLKS], bT[SCAN_BLKS];
#pragma unroll
        for (int b = 0; b < SCAN_BLKS; b++) { bU[b] = d_bU[b]; bT[b] = d_bT[b]; }
        int p = 0;
#pragma unroll
        for (int a = 0; a < N_ACT; a++) {
            pstS[a] = p;
            int ua = bU[a * 4] + bU[a * 4 + 1] + bU[a * 4 + 2] + bU[a * 4 + 3];
            p += ((ua + TILE_M - 1) / TILE_M) * TILE_M;
        }
        pstS[4] = p;
        if (blk == 0) {
#pragma unroll
            for (int a = 0; a <= N_ACT; a++) d_pstart[a] = pstS[a];
        }
        int a = blk >> 2;
        int u = pstS[a];
        for (int b = a * 4; b < blk; b++) u += bU[b];
        int r = 0;
        for (int b = 0; b < blk; b++) r += bT[b];
        base_u = u; base_r = r;
    }
    __syncthreads();

    const int k0 = (blk * 256 + t) * 4;
    int4 x = *(const int4*)(d_hist + k0);
    int h[4] = { x.x, x.y, x.z, x.w };
    int nu = (h[0] != 0) + (h[1] != 0) + (h[2] != 0) + (h[3] != 0);
    int nt = h[0] + h[1] + h[2] + h[3];
    int su = nu, st = nt;
#pragma unroll
    for (int o = 1; o < 32; o <<= 1) {
        int vu = __shfl_up_sync(~0u, su, o);
        int vt = __shfl_up_sync(~0u, st, o);
        if (lane >= o) { su += vu; st += vt; }
    }
    if (lane == 31) { wU[warp] = su; wT[warp] = st; }
    __syncthreads();
    int wexU = 0, wexT = 0;
    for (int w = 0; w < warp; w++) { wexU += wU[w]; wexT += wT[w]; }
    int u = base_u + wexU + (su - nu);
    int r = base_r + wexT + (st - nt);
#pragma unroll
    for (int i = 0; i < 4; i++) {
        int k = k0 + i;
        if (h[i]) {
            d_roff[k] = r;
            d_srow[u] = k & (NSTATES - 1);
            d_uroff[u] = r; d_ucnt[u] = h[i];
            u++; r += h[i];
        }
    }
}

__global__ void k_scatter(const int* __restrict__ act, const int* __restrict__ state) {
    int i = blockIdx.x * 256 + threadIdx.x;
    int key = act[i] * NSTATES + state[i];
    int pos = atomicAdd(&d_cur[key], 1);
    d_rows[d_roff[key] + pos] = i;
}

// gather emb rows into unique fp16 buffer d_Ge (zeros for pad rows)
__global__ void k_gather(const float* __restrict__ emb) {
    int i = blockIdx.x * 256 + threadIdx.x;     // one uint4 (8 halves) per thread
    int krow = i / (GTOT / 8);
    int cu   = i - krow * (GTOT / 8);
    if (krow >= d_pstart[4]) return;
    int srow = d_srow[krow];
    uint4 h;
    if (srow >= 0) {
        const float4* p = (const float4*)(emb + (size_t)srow * GTOT + cu * 8);
        float4 x0 = p[0], x1 = p[1];
        h.x = pack_h2(x0.x, x0.y); h.y = pack_h2(x0.z, x0.w);
        h.z = pack_h2(x1.x, x1.y); h.w = pack_h2(x1.z, x1.w);
    } else {
        h = make_uint4(0, 0, 0, 0);
    }
    *(uint4*)(d_Ge + (size_t)krow * GTOT + cu * 8) = h;
}

// ============================================================================
// Shared GEMM building blocks (BM=BN=128, BK=64, 256 threads, 8 warps 2Mx4N)
// 3-stage cp.async pipeline, ONE __syncthreads per K-iter.
// ============================================================================
__device__ __forceinline__ void load_tile64(uint32_t sDst, const __half* gBase,
                                            int rowStride, int kofs, int tid) {
#pragma unroll
    for (int i = 0; i < 4; i++) {
        int idx = tid + i * 256;            // 0..1023 -> 128 rows x 8 16B chunks
        int row = idx >> 3, cb = idx & 7;
        cp_async16(sDst + (uint32_t)(row * SROW + cb * 8) * 2u,
                   gBase + (size_t)row * rowStride + kofs + cb * 8);
    }
}

__device__ __forceinline__ void gemm_stage64(uint32_t sA, uint32_t sB, int wm, int wn,
                                             int lane, float (*c)[4][4]) {
#pragma unroll
    for (int ks = 0; ks < 4; ks++) {
        uint32_t a[4][4];
#pragma unroll
        for (int mt = 0; mt < 4; mt++) {
            int row = wm * 64 + mt * 16 + (lane & 15);
            int col = ks * 16 + ((lane >> 4) << 3);
            ldsm_x4(a[mt], sA + (uint32_t)(row * SROW + col) * 2u);
        }
#pragma unroll
        for (int g2 = 0; g2 < 2; g2++) {
            uint32_t b[4];
            int nrow = wn * 32 + g2 * 16 + (lane & 7) + ((lane >> 4) & 1) * 8;
            int col  = ks * 16 + ((lane >> 3) & 1) * 8;
            ldsm_x4(b, sB + (uint32_t)(nrow * SROW + col) * 2u);
#pragma unroll
            for (int mt = 0; mt < 4; mt++) {
                mma16816(c[mt][g2 * 2 + 0], a[mt], b[0], b[1]);
                mma16816(c[mt][g2 * 2 + 1], a[mt], b[2], b[3]);
            }
        }
    }
}

// ============================================================================
// Transition kernel: per (128-row unique tile, module-coltile) HMMA GEMM
//   delta[r,j] = sum_i g[r,i] * D[a][j,i];  g_next = clip(g + delta, -1, 1)
// grid.y jobs: 0,1 -> f0 col0/1; 2,3 -> f1 col0/1; 4 -> f2; 5 -> f3
// ============================================================================
__global__ void __launch_bounds__(256, 2) k_trans(float* __restrict__ outg) {
    extern __shared__ __align__(16) __half sm[];
    const int row0 = blockIdx.x * TILE_M;
    if (row0 >= d_pstart[4]) return;
    const int jy = blockIdx.y;
    const int f    = (jy < 2) ? 0 : (jy < 4) ? 1 : (jy == 4) ? 2 : 3;
    const int ct   = (jy == 1 || jy == 3) ? 1 : 0;
    const int n    = (f < 2) ? 256 : 128;
    const int koff = (f == 0) ? 0 : (f == 1) ? 256 : (f == 2) ? 512 : 640;
    const int moff = (f == 0) ? 0 : (f == 1) ? 262144 : (f == 2) ? 524288 : 589824;
    const int col0 = ct * 128;

    int a = 0;
    { int p1 = d_pstart[1], p2 = d_pstart[2], p3 = d_pstart[3];
      if (row0 >= p3) a = 3; else if (row0 >= p2) a = 2; else if (row0 >= p1) a = 1; }

    const int tid = threadIdx.x, lane = tid & 31, wid = tid >> 5;
    const int wm = wid & 1, wn = wid >> 1;
    uint32_t sb = smem_to_u32(sm);
    uint32_t sA[3] = { sb, sb + STAGE_B, sb + 2*STAGE_B };
    uint32_t sB[3] = { sb + 3*STAGE_B, sb + 4*STAGE_B, sb + 5*STAGE_B };

    const __half* Ab = d_Ge + (size_t)row0 * GTOT + koff;
    const __half* Bb = d_Dh + (size_t)moff + (size_t)a * n * n + (size_t)col0 * n;

    float c[4][4][4];
#pragma unroll
    for (int i = 0; i < 4; i++)
#pragma unroll
        for (int j = 0; j < 4; j++)
#pragma unroll
            for (int e = 0; e < 4; e++) c[i][j][e] = 0.0f;

    const int KT = n >> 6;      // 4 or 2
    load_tile64(sA[0], Ab, GTOT, 0, tid);
    load_tile64(sB[0], Bb, n,    0, tid);
    CP_COMMIT();
    load_tile64(sA[1], Ab, GTOT, 64, tid);
    load_tile64(sB[1], Bb, n,    64, tid);
    CP_COMMIT();
    for (int kc = 0; kc < KT; kc++) {
        CP_WAIT(1);
        __syncthreads();
        int nx = kc + 2;
        if (nx < KT) {
            int b3 = nx % 3;
            load_tile64(sA[b3], Ab, GTOT, nx * 64, tid);
            load_tile64(sB[b3], Bb, n,    nx * 64, tid);
        }
        CP_COMMIT();
        gemm_stage64(sA[kc % 3], sB[kc % 3], wm, wn, lane, c);
    }

    // epilogue: gn = clip(g + delta); fp16 to unique buf, fp32 fan-out to dup rows
#pragma unroll
    for (int mt = 0; mt < 4; mt++) {
#pragma unroll
        for (int e2 = 0; e2 < 2; e2++) {
            int krow = row0 + wm * 64 + mt * 16 + (lane >> 2) + e2 * 8;
            int cnt  = d_ucnt[krow];
            int roff = d_uroff[krow];
            int cbase = koff + col0 + wn * 32 + 2 * (lane & 3);
            const __half* gp = d_Ge + (size_t)krow * GTOT + cbase;
            __half*       hp = d_Gh + (size_t)krow * GTOT + cbase;
            float2 vals[4];
#pragma unroll
            for (int ng = 0; ng < 4; ng++) {
                __half2 g2v = *(const __half2*)(gp + ng * 8);
                float vx = __low2float(g2v)  + c[mt][ng][e2 * 2 + 0];
                float vy = __high2float(g2v) + c[mt][ng][e2 * 2 + 1];
                vx = fminf(1.0f, fmaxf(-1.0f, vx));
                vy = fminf(1.0f, fmaxf(-1.0f, vy));
                *(__half2*)(hp + ng * 8) = __floats2half2_rn(vx, vy);
                vals[ng].x = vx; vals[ng].y = vy;
            }
            for (int j = 0; j < cnt; j++) {
                int orow = d_rows[roff + j];
                float* op = outg + (size_t)orow * GTOT + cbase;
#pragma unroll
                for (int ng = 0; ng < 4; ng++)
                    st_cs_f2(op + ng * 8, vals[ng]);
            }
        }
    }
}

// ============================================================================
// Classifier kernel: logits = g_next @ W^T + b   (128x128 tiles, K=768, BK=64)
// 256 threads, 2 CTAs/SM, 3-stage pipeline
// ============================================================================
__global__ void __launch_bounds__(256, 2) k_cls(const float* __restrict__ bias,
                                                float* __restrict__ out) {
    extern __shared__ __align__(16) __half sm[];
    const int row0 = blockIdx.x * TILE_M;
    if (row0 >= d_pstart[4]) return;
    const int col0 = blockIdx.y * 128;

    const int tid = threadIdx.x, lane = tid & 31, wid = tid >> 5;
    const int wm = wid & 1, wn = wid >> 1;
    uint32_t sb = smem_to_u32(sm);
    uint32_t sA[3] = { sb, sb + STAGE_B, sb + 2*STAGE_B };
    uint32_t sB[3] = { sb + 3*STAGE_B, sb + 4*STAGE_B, sb + 5*STAGE_B };

    const __half* Ab = d_Gh + (size_t)row0 * GTOT;
    const __half* Bb = d_Wh + (size_t)col0 * GTOT;

    float c[4][4][4];
#pragma unroll
    for (int i = 0; i < 4; i++)
#pragma unroll
        for (int j = 0; j < 4; j++)
#pragma unroll
            for (int e = 0; e < 4; e++) c[i][j][e] = 0.0f;

    const int KT = GTOT >> 6;   // 12
    load_tile64(sA[0], Ab, GTOT, 0, tid);
    load_tile64(sB[0], Bb, GTOT, 0, tid);
    CP_COMMIT();
    load_tile64(sA[1], Ab, GTOT, 64, tid);
    load_tile64(sB[1], Bb, GTOT, 64, tid);
    CP_COMMIT();
    for (int kc = 0; kc < KT; kc++) {
        CP_WAIT(1);
        __syncthreads();
        int nx = kc + 2;
        if (nx < KT) {
            int b3 = nx % 3;
            load_tile64(sA[b3], Ab, GTOT, nx * 64, tid);
            load_tile64(sB[b3], Bb, GTOT, nx * 64, tid);
        }
        CP_COMMIT();
        gemm_stage64(sA[kc % 3], sB[kc % 3], wm, wn, lane, c);
    }

    // epilogue: add bias, fan logits out to all duplicate original rows
#pragma unroll
    for (int mt = 0; mt < 4; mt++) {
#pragma unroll
        for (int e2 = 0; e2 < 2; e2++) {
            int krow = row0 + wm * 64 + mt * 16 + (lane >> 2) + e2 * 8;
            int cnt  = d_ucnt[krow];
            if (cnt == 0) continue;
            int roff = d_uroff[krow];
            int cbase = col0 + wn * 32 + 2 * (lane & 3);
            float2 vals[4];
#pragma unroll
            for (int ng = 0; ng < 4; ng++) {
                float2 bv = *(const float2*)(bias + cbase + ng * 8);
                vals[ng].x = c[mt][ng][e2 * 2 + 0] + bv.x;
                vals[ng].y = c[mt][ng][e2 * 2 + 1] + bv.y;
            }
            for (int j = 0; j < cnt; j++) {
                int orow = d_rows[roff + j];
                float* op = out + (size_t)orow * NSTATES + cbase;
#pragma unroll
                for (int ng = 0; ng < 4; ng++)
                    st_cs_f2(op + ng * 8, vals[ng]);
            }
        }
    }
}

// ============================================================================
// Host launch (graph-capturable: kernel launches + event fork/join only)
// ============================================================================
extern "C" void kernel_launch(void* const* d_in, const int* in_sizes, int n_in,
                              void* d_out, int out_size) {
    // Identify inputs by element count (unambiguous for this problem):
    //   16384 (x2): current_state_index, action_index   (metadata order: state first)
    //   3145728 (x2): emb, W_cls      4096: b_cls
    //   262144 (x2): D0, D1           65536 (x2): D2, D3
    const int *state = nullptr, *act = nullptr;
    const float *emb = nullptr, *W = nullptr, *bias = nullptr;
    const float *D0 = nullptr, *D1 = nullptr, *D2 = nullptr, *D3 = nullptr;
    for (int i = 0; i < n_in; i++) {
        int s = in_sizes[i];
        const void* p = d_in[i];
        if      (s == 16384)   { if (!state) state = (const int*)p; else act = (const int*)p; }
        else if (s == 3145728) { if (!emb)   emb   = (const float*)p; else W = (const float*)p; }
        else if (s == 4096)    { bias = (const float*)p; }
        else if (s == 262144)  { if (!D0) D0 = (const float*)p; else D1 = (const float*)p; }
        else if (s == 65536)   { if (!D2) D2 = (const float*)p; else D3 = (const float*)p; }
    }

    float* out  = (float*)d_out;                       // logits [16384, 4096]
    float* outg = out + (size_t)B_TOTAL * NSTATES;     // g_next [16384, 768]

    // Stream/events created on FIRST (uncaptured, correctness) call only.
    static cudaStream_t s1 = nullptr;
    static cudaEvent_t eFork = nullptr, eJoin = nullptr;
    if (!s1) {
        cudaStreamCreateWithFlags(&s1, cudaStreamNonBlocking);
        cudaEventCreateWithFlags(&eFork, cudaEventDisableTiming);
        cudaEventCreateWithFlags(&eJoin, cudaEventDisableTiming);
        cudaFuncSetAttribute(k_trans, cudaFuncAttributeMaxDynamicSharedMemorySize, SMEM_P);
        cudaFuncSetAttribute(k_cls,   cudaFuncAttributeMaxDynamicSharedMemorySize, SMEM_P);
    }

    k_init<<<640, 256>>>(D0, D1, D2, D3);              // zero/init + D convert

    // fork: W convert overlaps the sort chain + k_trans (only k_cls reads d_Wh)
    cudaEventRecord(eFork, 0);
    cudaStreamWaitEvent(s1, eFork, 0);
    k_convW<<<3072, 256, 0, s1>>>(W);
    cudaEventRecord(eJoin, s1);

    k_hist<<<64, 256>>>(act, state);
    k_scanA<<<SCAN_BLKS, 256>>>();
    k_scanB<<<SCAN_BLKS, 256>>>();
    k_scatter<<<64, 256>>>(act, state);
    k_gather<<<P_MAX * (GTOT / 8) / 256, 256>>>(emb);
    k_trans<<<dim3(MAX_TILES, 6), 256, SMEM_P>>>(outg);

    cudaStreamWaitEvent(0, eJoin, 0);                  // join before k_cls
    k_cls<<<dim3(MAX_TILES, 32), 256, SMEM_P>>>(bias, out);
}